// round 2
// baseline (speedup 1.0000x reference)
#include <cuda_runtime.h>
#include <cuda_bf16.h>
#include <cstdint>

// FeatureVectorInteractions: B=4096, N=128, D=64
// out[b] = dot( sum_i m0[b,i]*V0[b,i,:], sum_j m1[b,j]*V1[b,j,:] )
// m = (vi > 0) since vi in [0,1000) and clip(vi,0,1).
//
// One CTA per batch. 256 threads: v = tid&15 selects float4 column (4 dims),
// rg = tid>>4 selects row group; each thread accumulates 8 rows of V0 and V1.
// Fully coalesced LDG.128 streams; HBM-bound.

#define NROWS 128
#define NV4   16   // 64 floats = 16 float4 per row

__global__ __launch_bounds__(256, 8)
void fvi_kernel(const int* __restrict__ VI0,
                const int* __restrict__ VI1,
                const float* __restrict__ V0,
                const float* __restrict__ V1,
                float* __restrict__ out)
{
    const int b   = blockIdx.x;
    const int tid = threadIdx.x;

    __shared__ float m0s[NROWS];
    __shared__ float m1s[NROWS];
    __shared__ float4 red0[256];
    __shared__ float4 red1[256];

    // Load masks: first 128 threads -> m0, next 128 -> m1
    if (tid < NROWS) {
        m0s[tid] = (VI0[b * NROWS + tid] > 0) ? 1.0f : 0.0f;
    } else {
        int r = tid - NROWS;
        m1s[r] = (VI1[b * NROWS + r] > 0) ? 1.0f : 0.0f;
    }
    __syncthreads();

    const float4* v0 = (const float4*)(V0 + (size_t)b * NROWS * 64);
    const float4* v1 = (const float4*)(V1 + (size_t)b * NROWS * 64);

    const int v  = tid & 15;   // float4 column
    const int rg = tid >> 4;   // row group 0..15

    float4 a0 = make_float4(0.f, 0.f, 0.f, 0.f);
    float4 a1 = make_float4(0.f, 0.f, 0.f, 0.f);

    #pragma unroll
    for (int r = 0; r < 8; r++) {
        int row = rg + r * 16;              // rows strided so each half-warp is contiguous
        float  m0 = m0s[row];
        float  m1 = m1s[row];
        float4 x0 = v0[row * NV4 + v];
        float4 x1 = v1[row * NV4 + v];
        a0.x += m0 * x0.x; a0.y += m0 * x0.y; a0.z += m0 * x0.z; a0.w += m0 * x0.w;
        a1.x += m1 * x1.x; a1.y += m1 * x1.y; a1.z += m1 * x1.z; a1.w += m1 * x1.w;
    }

    red0[rg * 16 + v] = a0;
    red1[rg * 16 + v] = a1;
    __syncthreads();

    if (tid < 16) {
        // reduce over the 16 row groups for float4-column tid
        float4 u0 = red0[tid];
        float4 u1 = red1[tid];
        #pragma unroll
        for (int g = 1; g < 16; g++) {
            float4 p0 = red0[g * 16 + tid];
            float4 p1 = red1[g * 16 + tid];
            u0.x += p0.x; u0.y += p0.y; u0.z += p0.z; u0.w += p0.w;
            u1.x += p1.x; u1.y += p1.y; u1.z += p1.z; u1.w += p1.w;
        }
        // partial dot over this thread's 4 dims
        float p = u0.x * u1.x + u0.y * u1.y + u0.z * u1.z + u0.w * u1.w;
        // reduce 16 lanes (all within warp 0)
        #pragma unroll
        for (int off = 8; off >= 1; off >>= 1)
            p += __shfl_xor_sync(0x0000FFFFu, p, off, 16);
        if (tid == 0) out[b] = p;
    }
}

extern "C" void kernel_launch(void* const* d_in, const int* in_sizes, int n_in,
                              void* d_out, int out_size)
{
    const int*   VI0 = (const int*)d_in[0];
    const int*   VI1 = (const int*)d_in[1];
    const float* V0  = (const float*)d_in[2];
    const float* V1  = (const float*)d_in[3];
    float*       out = (float*)d_out;

    // B from V0 element count (B*128*64) — robust to mask-size assumptions.
    const int B = in_sizes[2] / (NROWS * 64);
    fvi_kernel<<<B, 256>>>(VI0, VI1, V0, V1, out);
}